// round 13
// baseline (speedup 1.0000x reference)
#include <cuda_runtime.h>
#include <cuda_fp16.h>
#include <cuda_bf16.h>
#include <stdint.h>

// Problem shape (fixed by the reference)
#define BATCH 4
#define SEQ   2048
#define EMB   1024

// ---------------- scratch (device globals; no cudaMalloc allowed) ----------
__device__ __half d_Qh[(size_t)BATCH * SEQ * EMB];           // 16 MB (Q * 1/32)
__device__ __half d_Kh[(size_t)BATCH * SEQ * EMB];           // 16 MB
__device__ __half d_Vt[(size_t)BATCH * SEQ * EMB];           // 16 MB (V^T: [B][E][S])
__device__ __half d_Sh[(size_t)BATCH * SEQ * SEQ];           // 32 MB (scores fp16)
__device__ __half d_P [(size_t)BATCH * SEQ * SEQ];           // 32 MB (softmax probs fp16)

// ---------------- fused prep: Q/K convert + V transpose, ONE launch ---------
__global__ void __launch_bounds__(256)
prep(const float* __restrict__ Q, const float* __restrict__ K,
     const float* __restrict__ V,
     __half* __restrict__ Qh, __half* __restrict__ Kh, __half* __restrict__ Vt)
{
    __shared__ float tile[32][33];

    if (blockIdx.y == 0) {
        const bool isK   = blockIdx.x >= 4096;
        const float* in  = isK ? K : Q;
        __half*      out = isK ? Kh : Qh;
        const float scale = isK ? 1.0f : 0.03125f;   // 1/sqrt(1024) folded into Q
        long base = ((long)(blockIdx.x & 4095) * 256 + threadIdx.x) * 8;
        float4 v0 = *reinterpret_cast<const float4*>(in + base);
        float4 v1 = *reinterpret_cast<const float4*>(in + base + 4);
        __half h[8];
        h[0] = __float2half_rn(v0.x * scale); h[1] = __float2half_rn(v0.y * scale);
        h[2] = __float2half_rn(v0.z * scale); h[3] = __float2half_rn(v0.w * scale);
        h[4] = __float2half_rn(v1.x * scale); h[5] = __float2half_rn(v1.y * scale);
        h[6] = __float2half_rn(v1.z * scale); h[7] = __float2half_rn(v1.w * scale);
        *reinterpret_cast<uint4*>(out + base) = *reinterpret_cast<const uint4*>(h);
    } else {
        const int b  = blockIdx.x >> 11;
        const int t  = blockIdx.x & 2047;
        const int e0 = (t & 31) * 32;
        const int j0 = (t >> 5) * 32;
        const int tx = threadIdx.x & 31;
        const int ty = threadIdx.x >> 5;
        const float* Vb  = V  + (size_t)b * SEQ * EMB;
        __half*      Vtb = Vt + (size_t)b * SEQ * EMB;
        for (int r = ty; r < 32; r += 8)
            tile[r][tx] = Vb[(size_t)(j0 + r) * EMB + e0 + tx];
        __syncthreads();
        for (int r = ty; r < 32; r += 8)
            Vtb[(size_t)(e0 + r) * SEQ + j0 + tx] = __float2half_rn(tile[tx][r]);
    }
}

// ---------------- helpers ---------------------------------------------------
__device__ __forceinline__ uint32_t smem_u32(const void* p)
{
    uint32_t a;
    asm("{ .reg .u64 t; cvta.to.shared.u64 t, %1; cvt.u32.u64 %0, t; }" : "=r"(a) : "l"(p));
    return a;
}

__device__ __forceinline__ void cp_async16(uint32_t dst, const void* src)
{
    asm volatile("cp.async.cg.shared.global [%0], [%1], 16;" :: "r"(dst), "l"(src));
}
#define CP_COMMIT() asm volatile("cp.async.commit_group;" ::: "memory")
#define CP_WAIT(n)  asm volatile("cp.async.wait_group %0;" :: "n"(n) : "memory")

__device__ __forceinline__ void ldsm_x4_u(uint32_t& r0, uint32_t& r1, uint32_t& r2, uint32_t& r3,
                                          uint32_t sa)
{
    asm volatile("ldmatrix.sync.aligned.m8n8.x4.shared.b16 {%0,%1,%2,%3}, [%4];"
                 : "=r"(r0), "=r"(r1), "=r"(r2), "=r"(r3) : "r"(sa));
}

__device__ __forceinline__ void mma16816(float* d, const uint32_t* a, const uint32_t* b)
{
    asm("mma.sync.aligned.m16n8k16.row.col.f32.f16.f16.f32 "
        "{%0,%1,%2,%3}, {%4,%5,%6,%7}, {%8,%9}, {%0,%1,%2,%3};"
        : "+f"(d[0]), "+f"(d[1]), "+f"(d[2]), "+f"(d[3])
        : "r"(a[0]), "r"(a[1]), "r"(a[2]), "r"(a[3]), "r"(b[0]), "r"(b[1]));
}

// fp16-accumulate variant: D,C are 2 regs (half2 pairs)
__device__ __forceinline__ void mma16816h(uint32_t* d, const uint32_t* a, const uint32_t* b)
{
    asm("mma.sync.aligned.m16n8k16.row.col.f16.f16.f16.f16 "
        "{%0,%1}, {%2,%3,%4,%5}, {%6,%7}, {%0,%1};"
        : "+r"(d[0]), "+r"(d[1])
        : "r"(a[0]), "r"(a[1]), "r"(a[2]), "r"(a[3]), "r"(b[0]), "r"(b[1]));
}

// ---------------- GEMM common: 128x128 tile, BK=64, 2-stage cp.async --------
#define BM 128
#define BN 128
#define BKT 64
#define ROWB   144                       // bytes per smem row (72 halfs)
#define ABYT   (BM * ROWB)               // 18432
#define STGB   (2 * ABYT)                // 36864 per stage (A + B)
#define GEMM_DSMEM (2 * STGB)            // 73728

#define CPLOAD(Ab, Bb, Kdim, c, s)                                                        \
    {                                                                                     \
        uint32_t so = (uint32_t)((s) * STGB);                                             \
        const __half* a0 = (Ab) + (size_t)(tm + (tid >> 3)) * (Kdim) + (c) * BKT + (tid & 7) * 8; \
        const __half* b0 = (Bb) + (size_t)(tn + (tid >> 3)) * (Kdim) + (c) * BKT + (tid & 7) * 8; \
        uint32_t d0 = sbase + so + (uint32_t)((tid >> 3) * ROWB + (tid & 7) * 16);        \
        _Pragma("unroll")                                                                 \
        for (int r = 0; r < 4; ++r) {                                                     \
            cp_async16(d0 + (uint32_t)(r * 32 * ROWB),        a0 + (size_t)(r * 32) * (Kdim)); \
            cp_async16(d0 + ABYT + (uint32_t)(r * 32 * ROWB), b0 + (size_t)(r * 32) * (Kdim)); \
        }                                                                                 \
    }

// fp32-acc mainloop (R9/R12 winner) — used by gemm_s
#define GEMM_MAINLOOP(Ab, Bb, Kdim)                                                       \
    {                                                                                     \
        const int NC = (Kdim) / BKT;                                                      \
        CPLOAD(Ab, Bb, Kdim, 0, 0) CP_COMMIT();                                           \
        CPLOAD(Ab, Bb, Kdim, 1, 1) CP_COMMIT();                                           \
        for (int c = 0; c < NC; ++c) {                                                    \
            if (c + 1 < NC) { CP_WAIT(1); } else { CP_WAIT(0); }                          \
            __syncthreads();                                                              \
            const uint32_t so = (uint32_t)((c & 1) * STGB);                               \
            _Pragma("unroll")                                                             \
            for (int kk = 0; kk < BKT; kk += 16) {                                        \
                uint32_t af[4][4];                                                        \
                uint32_t bf[4][2];                                                        \
                _Pragma("unroll")                                                         \
                for (int mt = 0; mt < 4; ++mt)                                            \
                    ldsm_x4_u(af[mt][0], af[mt][1], af[mt][2], af[mt][3],                 \
                              sbase + so + (uint32_t)((wm + mt * 16 + (lane & 15)) * ROWB \
                                                      + (kk + ((lane >> 4) << 3)) * 2));  \
                _Pragma("unroll")                                                         \
                for (int nb = 0; nb < 2; ++nb) {                                          \
                    uint32_t r0, r1, r2, r3;                                              \
                    ldsm_x4_u(r0, r1, r2, r3,                                             \
                              sbase + so + ABYT + (uint32_t)((wn + nb * 16 + (lane & 15)) * ROWB \
                                                      + (kk + ((lane >> 4) << 3)) * 2));  \
                    bf[nb * 2 + 0][0] = r0; bf[nb * 2 + 0][1] = r2;                       \
                    bf[nb * 2 + 1][0] = r1; bf[nb * 2 + 1][1] = r3;                       \
                }                                                                         \
                _Pragma("unroll")                                                         \
                for (int mt = 0; mt < 4; ++mt)                                            \
                    _Pragma("unroll")                                                     \
                    for (int nt = 0; nt < 4; ++nt)                                        \
                        mma16816(acc[mt][nt], af[mt], bf[nt]);                            \
            }                                                                             \
            __syncthreads();                                                              \
            if (c + 2 < NC) { CPLOAD(Ab, Bb, Kdim, c + 2, (c & 1)) CP_COMMIT(); }         \
        }                                                                                 \
    }

// ---------------- GEMM1: S = (Qs) @ K^T, fp32 acc, fp16 out -----------------
__global__ void __launch_bounds__(256, 2)
gemm_s(const __half* __restrict__ A, const __half* __restrict__ B,
       __half* __restrict__ S)
{
    extern __shared__ char dsm[];
    const uint32_t sbase = smem_u32(dsm);

    const int b = blockIdx.z;
    const __half* Ab = A + (size_t)b * SEQ * EMB;
    const __half* Bb = B + (size_t)b * SEQ * EMB;
    __half*       Sb = S + (size_t)b * SEQ * SEQ;

    const int tm = blockIdx.y * BM;
    const int tn = blockIdx.x * BN;
    const int tid  = threadIdx.x;
    const int wid  = tid >> 5;
    const int lane = tid & 31;
    const int wm = (wid & 1) * 64;
    const int wn = (wid >> 1) * 32;

    float acc[4][4][4];
#pragma unroll
    for (int i = 0; i < 4; i++)
#pragma unroll
        for (int j = 0; j < 4; j++)
#pragma unroll
            for (int k = 0; k < 4; k++) acc[i][j][k] = 0.f;

    GEMM_MAINLOOP(Ab, Bb, EMB)

#pragma unroll
    for (int mt = 0; mt < 4; ++mt) {
#pragma unroll
        for (int nt = 0; nt < 4; ++nt) {
            int r = tm + wm + mt * 16 + (lane >> 2);
            int c = tn + wn + nt * 8 + ((lane & 3) << 1);
            *reinterpret_cast<__half2*>(&Sb[(size_t)r * SEQ + c]) =
                __floats2half2_rn(acc[mt][nt][0], acc[mt][nt][1]);
            *reinterpret_cast<__half2*>(&Sb[(size_t)(r + 8) * SEQ + c]) =
                __floats2half2_rn(acc[mt][nt][2], acc[mt][nt][3]);
        }
    }
}

// ---------------- GEMM2: O = P @ Vt^T, fp16 acc (span 32), fp32 out ---------
// Register-budgeted drain: per (half-chunk, mt) the live set is
// acc(64) + bf(16) + af(8) + hacc(8) + misc ~ 111 regs -> fits 128-cap, 2 CTAs/SM.
__global__ void __launch_bounds__(256, 2)
gemm_o(const __half* __restrict__ A, const __half* __restrict__ B,
       float* __restrict__ C)
{
    extern __shared__ char dsm[];
    const uint32_t sbase = smem_u32(dsm);

    const int b = blockIdx.z;
    const __half* Ab = A + (size_t)b * SEQ * SEQ;   // P: K = SEQ
    const __half* Bb = B + (size_t)b * SEQ * EMB;   // Vt: K = SEQ
    float*        Cb = C + (size_t)b * SEQ * EMB;

    const int tm = blockIdx.y * BM;
    const int tn = blockIdx.x * BN;
    const int tid  = threadIdx.x;
    const int wid  = tid >> 5;
    const int lane = tid & 31;
    const int wm = (wid & 1) * 64;
    const int wn = (wid >> 1) * 32;

    float acc[4][4][4];
#pragma unroll
    for (int i = 0; i < 4; i++)
#pragma unroll
        for (int j = 0; j < 4; j++)
#pragma unroll
            for (int k = 0; k < 4; k++) acc[i][j][k] = 0.f;

    const int NC = SEQ / BKT;
    CPLOAD(Ab, Bb, SEQ, 0, 0) CP_COMMIT();
    CPLOAD(Ab, Bb, SEQ, 1, 1) CP_COMMIT();

    for (int c = 0; c < NC; ++c) {
        if (c + 1 < NC) { CP_WAIT(1); } else { CP_WAIT(0); }
        __syncthreads();
        const uint32_t so = (uint32_t)((c & 1) * STGB);

#pragma unroll
        for (int half_c = 0; half_c < 2; ++half_c) {
            const int kk0 = half_c * 32;
            // B fragments for both k-steps of this 32-span
            uint32_t bf[2][4][2];
#pragma unroll
            for (int ks = 0; ks < 2; ++ks) {
#pragma unroll
                for (int nb = 0; nb < 2; ++nb) {
                    uint32_t r0, r1, r2, r3;
                    ldsm_x4_u(r0, r1, r2, r3,
                              sbase + so + ABYT + (uint32_t)((wn + nb * 16 + (lane & 15)) * ROWB
                                                  + ((kk0 + ks * 16) + ((lane >> 4) << 3)) * 2));
                    bf[ks][nb * 2 + 0][0] = r0; bf[ks][nb * 2 + 0][1] = r2;
                    bf[ks][nb * 2 + 1][0] = r1; bf[ks][nb * 2 + 1][1] = r3;
                }
            }
#pragma unroll
            for (int mt = 0; mt < 4; ++mt) {
                uint32_t af[2][4];
#pragma unroll
                for (int ks = 0; ks < 2; ++ks)
                    ldsm_x4_u(af[ks][0], af[ks][1], af[ks][2], af[ks][3],
                              sbase + so + (uint32_t)((wm + mt * 16 + (lane & 15)) * ROWB
                                              + ((kk0 + ks * 16) + ((lane >> 4) << 3)) * 2));
                uint32_t hacc[4][2];
#pragma unroll
                for (int nt = 0; nt < 4; ++nt) { hacc[nt][0] = 0u; hacc[nt][1] = 0u; }
#pragma unroll
                for (int nt = 0; nt < 4; ++nt) mma16816h(hacc[nt], af[0], bf[0][nt]);
#pragma unroll
                for (int nt = 0; nt < 4; ++nt) mma16816h(hacc[nt], af[1], bf[1][nt]);
                // drain fp16 partials into fp32 accumulators
#pragma unroll
                for (int nt = 0; nt < 4; ++nt) {
                    float2 lo = __half22float2(*reinterpret_cast<__half2*>(&hacc[nt][0]));
                    float2 hi = __half22float2(*reinterpret_cast<__half2*>(&hacc[nt][1]));
                    acc[mt][nt][0] += lo.x; acc[mt][nt][1] += lo.y;
                    acc[mt][nt][2] += hi.x; acc[mt][nt][3] += hi.y;
                }
            }
        }
        __syncthreads();
        if (c + 2 < NC) { CPLOAD(Ab, Bb, SEQ, c + 2, (c & 1)) CP_COMMIT(); }
    }

#pragma unroll
    for (int mt = 0; mt < 4; ++mt) {
#pragma unroll
        for (int nt = 0; nt < 4; ++nt) {
            int r = tm + wm + mt * 16 + (lane >> 2);
            int c = tn + wn + nt * 8 + ((lane & 3) << 1);
            *reinterpret_cast<float2*>(&Cb[(size_t)r * EMB + c]) =
                make_float2(acc[mt][nt][0], acc[mt][nt][1]);
            *reinterpret_cast<float2*>(&Cb[(size_t)(r + 8) * EMB + c]) =
                make_float2(acc[mt][nt][2], acc[mt][nt][3]);
        }
    }
}

// ---------------- row softmax (+ mask): S fp16 -> P fp16 --------------------
__device__ __forceinline__ float warp_max(float v)
{
#pragma unroll
    for (int o = 16; o > 0; o >>= 1) v = fmaxf(v, __shfl_xor_sync(0xffffffffu, v, o));
    return v;
}
__device__ __forceinline__ float warp_sum(float v)
{
#pragma unroll
    for (int o = 16; o > 0; o >>= 1) v += __shfl_xor_sync(0xffffffffu, v, o);
    return v;
}

__global__ void __launch_bounds__(256)
softmax_kernel(const __half* __restrict__ S, const float* __restrict__ mask,
               __half* __restrict__ P)
{
    __shared__ float red[8];
    int row = blockIdx.x;                 // b*SEQ + i
    const __half* s = S    + (size_t)row * SEQ;
    const float*  m = mask + (size_t)row * SEQ;
    __half*       p = P    + (size_t)row * SEQ;

    int base = threadIdx.x * 8;
    float v[8];
    {
        uint4 raw = *reinterpret_cast<const uint4*>(s + base);
        const __half2* h2 = reinterpret_cast<const __half2*>(&raw);
        float4 ma = *reinterpret_cast<const float4*>(m + base);
        float4 mb = *reinterpret_cast<const float4*>(m + base + 4);
        float2 f0 = __half22float2(h2[0]);
        float2 f1 = __half22float2(h2[1]);
        float2 f2 = __half22float2(h2[2]);
        float2 f3 = __half22float2(h2[3]);
        v[0] = f0.x + ma.x; v[1] = f0.y + ma.y; v[2] = f1.x + ma.z; v[3] = f1.y + ma.w;
        v[4] = f2.x + mb.x; v[5] = f2.y + mb.y; v[6] = f3.x + mb.z; v[7] = f3.y + mb.w;
    }
    float mx = v[0];
#pragma unroll
    for (int i = 1; i < 8; i++) mx = fmaxf(mx, v[i]);
    mx = warp_max(mx);
    int wid = threadIdx.x >> 5, lane = threadIdx.x & 31;
    if (lane == 0) red[wid] = mx;
    __syncthreads();
    if (wid == 0) {
        float t = (lane < 8) ? red[lane] : -1e30f;
        t = warp_max(t);
        if (lane == 0) red[0] = t;
    }
    __syncthreads();
    mx = red[0];

    float sum = 0.f;
#pragma unroll
    for (int i = 0; i < 8; i++) { v[i] = __expf(v[i] - mx); sum += v[i]; }
    sum = warp_sum(sum);
    __syncthreads();
    if (lane == 0) red[wid] = sum;
    __syncthreads();
    if (wid == 0) {
        float t = (lane < 8) ? red[lane] : 0.f;
        t = warp_sum(t);
        if (lane == 0) red[0] = t;
    }
    __syncthreads();
    float inv = 1.0f / red[0];

    __half h[8];
#pragma unroll
    for (int i = 0; i < 8; i++) h[i] = __float2half_rn(v[i] * inv);
    *reinterpret_cast<uint4*>(p + base) = *reinterpret_cast<const uint4*>(h);
}

// ---------------- launch -----------------------------------------------------
extern "C" void kernel_launch(void* const* d_in, const int* in_sizes, int n_in,
                              void* d_out, int out_size)
{
    const float* Q    = (const float*)d_in[0];
    const float* K    = (const float*)d_in[1];
    const float* V    = (const float*)d_in[2];
    const float* mask = (const float*)d_in[3];
    float* out = (float*)d_out;

    void *pQh, *pKh, *pVt, *pSh, *pP;
    cudaGetSymbolAddress(&pQh, d_Qh);
    cudaGetSymbolAddress(&pKh, d_Kh);
    cudaGetSymbolAddress(&pVt, d_Vt);
    cudaGetSymbolAddress(&pSh, d_Sh);
    cudaGetSymbolAddress(&pP,  d_P);

    cudaFuncSetAttribute(gemm_s, cudaFuncAttributeMaxDynamicSharedMemorySize, GEMM_DSMEM);
    cudaFuncSetAttribute(gemm_o, cudaFuncAttributeMaxDynamicSharedMemorySize, GEMM_DSMEM);

    // fused Q/K convert + V transpose (single launch)
    prep<<<dim3(8192, 2), 256>>>(Q, K, V,
                                 (__half*)pQh, (__half*)pKh, (__half*)pVt);

    // S = (Q/32) @ K^T  (fp32 acc, fp16 out)
    gemm_s<<<dim3(SEQ / BN, SEQ / BM, BATCH), 256, GEMM_DSMEM>>>(
        (const __half*)pQh, (const __half*)pKh, (__half*)pSh);

    softmax_kernel<<<BATCH * SEQ, 256>>>((const __half*)pSh, mask, (__half*)pP);

    // O = P @ V  (fp16 acc span-32, fp32 out)
    gemm_o<<<dim3(EMB / BN, SEQ / BM, BATCH), 256, GEMM_DSMEM>>>(
        (const __half*)pP, (const __half*)pVt, out);
}

// round 14
// speedup vs baseline: 1.1321x; 1.1321x over previous
#include <cuda_runtime.h>
#include <cuda_fp16.h>
#include <cuda_bf16.h>
#include <stdint.h>

// Problem shape (fixed by the reference)
#define BATCH 4
#define SEQ   2048
#define EMB   1024

// ---------------- scratch (device globals; no cudaMalloc allowed) ----------
__device__ __half d_Qh[(size_t)BATCH * SEQ * EMB];           // 16 MB (Q * 1/32)
__device__ __half d_Kh[(size_t)BATCH * SEQ * EMB];           // 16 MB
__device__ __half d_Vt[(size_t)BATCH * SEQ * EMB];           // 16 MB (V^T: [B][E][S])
__device__ __half d_Sh[(size_t)BATCH * SEQ * SEQ];           // 32 MB (scores fp16)
__device__ __half d_P [(size_t)BATCH * SEQ * SEQ];           // 32 MB (softmax probs fp16)

// ---------------- prep: Q/K fp32 -> fp16 convert (single launch) ------------
__global__ void __launch_bounds__(256)
prep(const float* __restrict__ Q, const float* __restrict__ K,
     __half* __restrict__ Qh, __half* __restrict__ Kh)
{
    const bool isK   = blockIdx.x >= 4096;
    const float* in  = isK ? K : Q;
    __half*      out = isK ? Kh : Qh;
    const float scale = isK ? 1.0f : 0.03125f;   // 1/sqrt(1024) folded into Q
    long base = ((long)(blockIdx.x & 4095) * 256 + threadIdx.x) * 8;
    float4 v0 = *reinterpret_cast<const float4*>(in + base);
    float4 v1 = *reinterpret_cast<const float4*>(in + base + 4);
    __half h[8];
    h[0] = __float2half_rn(v0.x * scale); h[1] = __float2half_rn(v0.y * scale);
    h[2] = __float2half_rn(v0.z * scale); h[3] = __float2half_rn(v0.w * scale);
    h[4] = __float2half_rn(v1.x * scale); h[5] = __float2half_rn(v1.y * scale);
    h[6] = __float2half_rn(v1.z * scale); h[7] = __float2half_rn(v1.w * scale);
    *reinterpret_cast<uint4*>(out + base) = *reinterpret_cast<const uint4*>(h);
}

// ---------------- helpers ---------------------------------------------------
__device__ __forceinline__ uint32_t smem_u32(const void* p)
{
    uint32_t a;
    asm("{ .reg .u64 t; cvta.to.shared.u64 t, %1; cvt.u32.u64 %0, t; }" : "=r"(a) : "l"(p));
    return a;
}

__device__ __forceinline__ void cp_async16(uint32_t dst, const void* src)
{
    asm volatile("cp.async.cg.shared.global [%0], [%1], 16;" :: "r"(dst), "l"(src));
}
#define CP_COMMIT() asm volatile("cp.async.commit_group;" ::: "memory")
#define CP_WAIT(n)  asm volatile("cp.async.wait_group %0;" :: "n"(n) : "memory")

__device__ __forceinline__ void ldsm_x4_u(uint32_t& r0, uint32_t& r1, uint32_t& r2, uint32_t& r3,
                                          uint32_t sa)
{
    asm volatile("ldmatrix.sync.aligned.m8n8.x4.shared.b16 {%0,%1,%2,%3}, [%4];"
                 : "=r"(r0), "=r"(r1), "=r"(r2), "=r"(r3) : "r"(sa));
}

__device__ __forceinline__ void mma16816(float* d, const uint32_t* a, const uint32_t* b)
{
    asm("mma.sync.aligned.m16n8k16.row.col.f32.f16.f16.f32 "
        "{%0,%1,%2,%3}, {%4,%5,%6,%7}, {%8,%9}, {%0,%1,%2,%3};"
        : "+f"(d[0]), "+f"(d[1]), "+f"(d[2]), "+f"(d[3])
        : "r"(a[0]), "r"(a[1]), "r"(a[2]), "r"(a[3]), "r"(b[0]), "r"(b[1]));
}

// ---------------- GEMM common: 128x128 tile, BK=64, 2-stage cp.async --------
#define BM 128
#define BN 128
#define BKT 64
#define ROWB   144                       // bytes per smem row (72 halfs)
#define ABYT   (BM * ROWB)               // 18432
#define STGB   (2 * ABYT)                // 36864 per stage (A + B)
#define GEMM_DSMEM (2 * STGB)            // 73728

#define CPLOAD(Ab, Bb, Kdim, c, s)                                                        \
    {                                                                                     \
        uint32_t so = (uint32_t)((s) * STGB);                                             \
        const __half* a0 = (Ab) + (size_t)(tm + (tid >> 3)) * (Kdim) + (c) * BKT + (tid & 7) * 8; \
        const __half* b0 = (Bb) + (size_t)(tn + (tid >> 3)) * (Kdim) + (c) * BKT + (tid & 7) * 8; \
        uint32_t d0 = sbase + so + (uint32_t)((tid >> 3) * ROWB + (tid & 7) * 16);        \
        _Pragma("unroll")                                                                 \
        for (int r = 0; r < 4; ++r) {                                                     \
            cp_async16(d0 + (uint32_t)(r * 32 * ROWB),        a0 + (size_t)(r * 32) * (Kdim)); \
            cp_async16(d0 + ABYT + (uint32_t)(r * 32 * ROWB), b0 + (size_t)(r * 32) * (Kdim)); \
        }                                                                                 \
    }

// fp32-acc 2-stage mainloop (R9/R12 winner)
#define GEMM_MAINLOOP(Ab, Bb, Kdim)                                                       \
    {                                                                                     \
        const int NC = (Kdim) / BKT;                                                      \
        CPLOAD(Ab, Bb, Kdim, 0, 0) CP_COMMIT();                                           \
        CPLOAD(Ab, Bb, Kdim, 1, 1) CP_COMMIT();                                           \
        for (int c = 0; c < NC; ++c) {                                                    \
            if (c + 1 < NC) { CP_WAIT(1); } else { CP_WAIT(0); }                          \
            __syncthreads();                                                              \
            const uint32_t so = (uint32_t)((c & 1) * STGB);                               \
            _Pragma("unroll")                                                             \
            for (int kk = 0; kk < BKT; kk += 16) {                                        \
                uint32_t af[4][4];                                                        \
                uint32_t bf[4][2];                                                        \
                _Pragma("unroll")                                                         \
                for (int mt = 0; mt < 4; ++mt)                                            \
                    ldsm_x4_u(af[mt][0], af[mt][1], af[mt][2], af[mt][3],                 \
                              sbase + so + (uint32_t)((wm + mt * 16 + (lane & 15)) * ROWB \
                                                      + (kk + ((lane >> 4) << 3)) * 2));  \
                _Pragma("unroll")                                                         \
                for (int nb = 0; nb < 2; ++nb) {                                          \
                    uint32_t r0, r1, r2, r3;                                              \
                    ldsm_x4_u(r0, r1, r2, r3,                                             \
                              sbase + so + ABYT + (uint32_t)((wn + nb * 16 + (lane & 15)) * ROWB \
                                                      + (kk + ((lane >> 4) << 3)) * 2));  \
                    bf[nb * 2 + 0][0] = r0; bf[nb * 2 + 0][1] = r2;                       \
                    bf[nb * 2 + 1][0] = r1; bf[nb * 2 + 1][1] = r3;                       \
                }                                                                         \
                _Pragma("unroll")                                                         \
                for (int mt = 0; mt < 4; ++mt)                                            \
                    _Pragma("unroll")                                                     \
                    for (int nt = 0; nt < 4; ++nt)                                        \
                        mma16816(acc[mt][nt], af[mt], bf[nt]);                            \
            }                                                                             \
            __syncthreads();                                                              \
            if (c + 2 < NC) { CPLOAD(Ab, Bb, Kdim, c + 2, (c & 1)) CP_COMMIT(); }         \
        }                                                                                 \
    }

// ---------------- GEMM1: V-transpose prologue + S = (Qs)@K^T ----------------
// Each CTA first transposes 8 of the batch's 2048 V-tiles (one per warp,
// private 32x33 fp32 staging in dsmem), then runs the standard mainloop.
// The 48 MB transpose traffic rides gemm_s's idle DRAM (5% busy).
__global__ void __launch_bounds__(256, 2)
gemm_s(const __half* __restrict__ A, const __half* __restrict__ B,
       const float* __restrict__ V, __half* __restrict__ Vt,
       __half* __restrict__ S)
{
    extern __shared__ char dsm[];
    const uint32_t sbase = smem_u32(dsm);

    const int b = blockIdx.z;
    const int tid  = threadIdx.x;
    const int wid  = tid >> 5;
    const int lane = tid & 31;

    // ---- V transpose prologue: one 32x32 tile per warp ----
    {
        const int linear = blockIdx.y * gridDim.x + blockIdx.x;   // 0..255
        const int t  = linear * 8 + wid;                          // 0..2047
        const int e0 = (t & 31) * 32;
        const int j0 = (t >> 5) * 32;
        float* stg = reinterpret_cast<float*>(dsm) + wid * (32 * 33);
        const float* Vb  = V  + (size_t)b * SEQ * EMB;
        __half*      Vtb = Vt + (size_t)b * SEQ * EMB;
#pragma unroll 4
        for (int r = 0; r < 32; ++r)
            stg[r * 33 + lane] = Vb[(size_t)(j0 + r) * EMB + e0 + lane];
        __syncwarp();
#pragma unroll 4
        for (int r = 0; r < 32; ++r)
            Vtb[(size_t)(e0 + r) * SEQ + j0 + lane] = __float2half_rn(stg[lane * 33 + r]);
    }
    __syncthreads();   // staging smem is reused by cp.async stages below

    const __half* Ab = A + (size_t)b * SEQ * EMB;
    const __half* Bb = B + (size_t)b * SEQ * EMB;
    __half*       Sb = S + (size_t)b * SEQ * SEQ;

    const int tm = blockIdx.y * BM;
    const int tn = blockIdx.x * BN;
    const int wm = (wid & 1) * 64;
    const int wn = (wid >> 1) * 32;

    float acc[4][4][4];
#pragma unroll
    for (int i = 0; i < 4; i++)
#pragma unroll
        for (int j = 0; j < 4; j++)
#pragma unroll
            for (int k = 0; k < 4; k++) acc[i][j][k] = 0.f;

    GEMM_MAINLOOP(Ab, Bb, EMB)

#pragma unroll
    for (int mt = 0; mt < 4; ++mt) {
#pragma unroll
        for (int nt = 0; nt < 4; ++nt) {
            int r = tm + wm + mt * 16 + (lane >> 2);
            int c = tn + wn + nt * 8 + ((lane & 3) << 1);
            *reinterpret_cast<__half2*>(&Sb[(size_t)r * SEQ + c]) =
                __floats2half2_rn(acc[mt][nt][0], acc[mt][nt][1]);
            *reinterpret_cast<__half2*>(&Sb[(size_t)(r + 8) * SEQ + c]) =
                __floats2half2_rn(acc[mt][nt][2], acc[mt][nt][3]);
        }
    }
}

// ---------------- GEMM2: O = P @ Vt^T, fp32 acc, fp32 out (R12 winner) ------
__global__ void __launch_bounds__(256, 2)
gemm_o(const __half* __restrict__ A, const __half* __restrict__ B,
       float* __restrict__ C)
{
    extern __shared__ char dsm[];
    const uint32_t sbase = smem_u32(dsm);

    const int b = blockIdx.z;
    const __half* Ab = A + (size_t)b * SEQ * SEQ;   // P: K = SEQ
    const __half* Bb = B + (size_t)b * SEQ * EMB;   // Vt: K = SEQ
    float*        Cb = C + (size_t)b * SEQ * EMB;

    const int tm = blockIdx.y * BM;
    const int tn = blockIdx.x * BN;
    const int tid  = threadIdx.x;
    const int wid  = tid >> 5;
    const int lane = tid & 31;
    const int wm = (wid & 1) * 64;
    const int wn = (wid >> 1) * 32;

    float acc[4][4][4];
#pragma unroll
    for (int i = 0; i < 4; i++)
#pragma unroll
        for (int j = 0; j < 4; j++)
#pragma unroll
            for (int k = 0; k < 4; k++) acc[i][j][k] = 0.f;

    GEMM_MAINLOOP(Ab, Bb, SEQ)

#pragma unroll
    for (int mt = 0; mt < 4; ++mt) {
#pragma unroll
        for (int nt = 0; nt < 4; ++nt) {
            int r = tm + wm + mt * 16 + (lane >> 2);
            int c = tn + wn + nt * 8 + ((lane & 3) << 1);
            *reinterpret_cast<float2*>(&Cb[(size_t)r * EMB + c]) =
                make_float2(acc[mt][nt][0], acc[mt][nt][1]);
            *reinterpret_cast<float2*>(&Cb[(size_t)(r + 8) * EMB + c]) =
                make_float2(acc[mt][nt][2], acc[mt][nt][3]);
        }
    }
}

// ---------------- row softmax (+ mask): S fp16 -> P fp16 --------------------
__device__ __forceinline__ float warp_max(float v)
{
#pragma unroll
    for (int o = 16; o > 0; o >>= 1) v = fmaxf(v, __shfl_xor_sync(0xffffffffu, v, o));
    return v;
}
__device__ __forceinline__ float warp_sum(float v)
{
#pragma unroll
    for (int o = 16; o > 0; o >>= 1) v += __shfl_xor_sync(0xffffffffu, v, o);
    return v;
}

__global__ void __launch_bounds__(256)
softmax_kernel(const __half* __restrict__ S, const float* __restrict__ mask,
               __half* __restrict__ P)
{
    __shared__ float red[8];
    int row = blockIdx.x;                 // b*SEQ + i
    const __half* s = S    + (size_t)row * SEQ;
    const float*  m = mask + (size_t)row * SEQ;
    __half*       p = P    + (size_t)row * SEQ;

    int base = threadIdx.x * 8;
    float v[8];
    {
        uint4 raw = *reinterpret_cast<const uint4*>(s + base);
        const __half2* h2 = reinterpret_cast<const __half2*>(&raw);
        float4 ma = *reinterpret_cast<const float4*>(m + base);
        float4 mb = *reinterpret_cast<const float4*>(m + base + 4);
        float2 f0 = __half22float2(h2[0]);
        float2 f1 = __half22float2(h2[1]);
        float2 f2 = __half22float2(h2[2]);
        float2 f3 = __half22float2(h2[3]);
        v[0] = f0.x + ma.x; v[1] = f0.y + ma.y; v[2] = f1.x + ma.z; v[3] = f1.y + ma.w;
        v[4] = f2.x + mb.x; v[5] = f2.y + mb.y; v[6] = f3.x + mb.z; v[7] = f3.y + mb.w;
    }
    float mx = v[0];
#pragma unroll
    for (int i = 1; i < 8; i++) mx = fmaxf(mx, v[i]);
    mx = warp_max(mx);
    int wid = threadIdx.x >> 5, lane = threadIdx.x & 31;
    if (lane == 0) red[wid] = mx;
    __syncthreads();
    if (wid == 0) {
        float t = (lane < 8) ? red[lane] : -1e30f;
        t = warp_max(t);
        if (lane == 0) red[0] = t;
    }
    __syncthreads();
    mx = red[0];

    float sum = 0.f;
#pragma unroll
    for (int i = 0; i < 8; i++) { v[i] = __expf(v[i] - mx); sum += v[i]; }
    sum = warp_sum(sum);
    __syncthreads();
    if (lane == 0) red[wid] = sum;
    __syncthreads();
    if (wid == 0) {
        float t = (lane < 8) ? red[lane] : 0.f;
        t = warp_sum(t);
        if (lane == 0) red[0] = t;
    }
    __syncthreads();
    float inv = 1.0f / red[0];

    __half h[8];
#pragma unroll
    for (int i = 0; i < 8; i++) h[i] = __float2half_rn(v[i] * inv);
    *reinterpret_cast<uint4*>(p + base) = *reinterpret_cast<const uint4*>(h);
}

// ---------------- launch -----------------------------------------------------
extern "C" void kernel_launch(void* const* d_in, const int* in_sizes, int n_in,
                              void* d_out, int out_size)
{
    const float* Q    = (const float*)d_in[0];
    const float* K    = (const float*)d_in[1];
    const float* V    = (const float*)d_in[2];
    const float* mask = (const float*)d_in[3];
    float* out = (float*)d_out;

    void *pQh, *pKh, *pVt, *pSh, *pP;
    cudaGetSymbolAddress(&pQh, d_Qh);
    cudaGetSymbolAddress(&pKh, d_Kh);
    cudaGetSymbolAddress(&pVt, d_Vt);
    cudaGetSymbolAddress(&pSh, d_Sh);
    cudaGetSymbolAddress(&pP,  d_P);

    cudaFuncSetAttribute(gemm_s, cudaFuncAttributeMaxDynamicSharedMemorySize, GEMM_DSMEM);
    cudaFuncSetAttribute(gemm_o, cudaFuncAttributeMaxDynamicSharedMemorySize, GEMM_DSMEM);

    // Q/K convert (single launch)
    prep<<<8192, 256>>>(Q, K, (__half*)pQh, (__half*)pKh);

    // V transpose (hidden in prologue) + S = (Q/32) @ K^T
    gemm_s<<<dim3(SEQ / BN, SEQ / BM, BATCH), 256, GEMM_DSMEM>>>(
        (const __half*)pQh, (const __half*)pKh, V, (__half*)pVt, (__half*)pSh);

    softmax_kernel<<<BATCH * SEQ, 256>>>((const __half*)pSh, mask, (__half*)pP);

    // O = P @ V  (fp32 acc)
    gemm_o<<<dim3(EMB / BN, SEQ / BM, BATCH), 256, GEMM_DSMEM>>>(
        (const __half*)pP, (const __half*)pVt, out);
}

// round 16
// speedup vs baseline: 1.1564x; 1.0214x over previous
#include <cuda_runtime.h>
#include <cuda_fp16.h>
#include <cuda_bf16.h>
#include <stdint.h>

// Problem shape (fixed by the reference)
#define BATCH 4
#define SEQ   2048
#define EMB   1024

// ---------------- scratch (device globals; no cudaMalloc allowed) ----------
__device__ __half d_Qh[(size_t)BATCH * SEQ * EMB];           // 16 MB (Q * 1/32)
__device__ __half d_Kh[(size_t)BATCH * SEQ * EMB];           // 16 MB
__device__ __half d_Vt[(size_t)BATCH * SEQ * EMB];           // 16 MB (V^T: [B][E][S])
__device__ __half d_E [(size_t)BATCH * SEQ * SEQ];           // 32 MB (exp(S+mask), fp16)
__device__ float  d_RS[(size_t)16 * BATCH * SEQ];            // 512 KB row-sum partials

// ---------------- prep: Q/K fp32 -> fp16 convert (single launch) ------------
__global__ void __launch_bounds__(256)
prep(const float* __restrict__ Q, const float* __restrict__ K,
     __half* __restrict__ Qh, __half* __restrict__ Kh)
{
    const bool isK   = blockIdx.x >= 4096;
    const float* in  = isK ? K : Q;
    __half*      out = isK ? Kh : Qh;
    const float scale = isK ? 1.0f : 0.03125f;   // 1/sqrt(1024) folded into Q
    long base = ((long)(blockIdx.x & 4095) * 256 + threadIdx.x) * 8;
    float4 v0 = *reinterpret_cast<const float4*>(in + base);
    float4 v1 = *reinterpret_cast<const float4*>(in + base + 4);
    __half h[8];
    h[0] = __float2half_rn(v0.x * scale); h[1] = __float2half_rn(v0.y * scale);
    h[2] = __float2half_rn(v0.z * scale); h[3] = __float2half_rn(v0.w * scale);
    h[4] = __float2half_rn(v1.x * scale); h[5] = __float2half_rn(v1.y * scale);
    h[6] = __float2half_rn(v1.z * scale); h[7] = __float2half_rn(v1.w * scale);
    *reinterpret_cast<uint4*>(out + base) = *reinterpret_cast<const uint4*>(h);
}

// ---------------- helpers ---------------------------------------------------
__device__ __forceinline__ uint32_t smem_u32(const void* p)
{
    uint32_t a;
    asm("{ .reg .u64 t; cvta.to.shared.u64 t, %1; cvt.u32.u64 %0, t; }" : "=r"(a) : "l"(p));
    return a;
}

__device__ __forceinline__ void cp_async16(uint32_t dst, const void* src)
{
    asm volatile("cp.async.cg.shared.global [%0], [%1], 16;" :: "r"(dst), "l"(src));
}
#define CP_COMMIT() asm volatile("cp.async.commit_group;" ::: "memory")
#define CP_WAIT(n)  asm volatile("cp.async.wait_group %0;" :: "n"(n) : "memory")

__device__ __forceinline__ void ldsm_x4_u(uint32_t& r0, uint32_t& r1, uint32_t& r2, uint32_t& r3,
                                          uint32_t sa)
{
    asm volatile("ldmatrix.sync.aligned.m8n8.x4.shared.b16 {%0,%1,%2,%3}, [%4];"
                 : "=r"(r0), "=r"(r1), "=r"(r2), "=r"(r3) : "r"(sa));
}

__device__ __forceinline__ void mma16816(float* d, const uint32_t* a, const uint32_t* b)
{
    asm("mma.sync.aligned.m16n8k16.row.col.f32.f16.f16.f32 "
        "{%0,%1,%2,%3}, {%4,%5,%6,%7}, {%8,%9}, {%0,%1,%2,%3};"
        : "+f"(d[0]), "+f"(d[1]), "+f"(d[2]), "+f"(d[3])
        : "r"(a[0]), "r"(a[1]), "r"(a[2]), "r"(a[3]), "r"(b[0]), "r"(b[1]));
}

// ---------------- GEMM common: 128x128 tile, BK=64, 2-stage cp.async --------
#define BM 128
#define BN 128
#define BKT 64
#define ROWB   144                       // bytes per smem row (72 halfs)
#define ABYT   (BM * ROWB)               // 18432
#define STGB   (2 * ABYT)                // 36864 per stage (A + B)
#define GEMM_DSMEM (2 * STGB)            // 73728  (also >= 128*132*4 = 67584)

#define CPLOAD(Ab, Bb, Kdim, c, s)                                                        \
    {                                                                                     \
        uint32_t so = (uint32_t)((s) * STGB);                                             \
        const __half* a0 = (Ab) + (size_t)(tm + (tid >> 3)) * (Kdim) + (c) * BKT + (tid & 7) * 8; \
        const __half* b0 = (Bb) + (size_t)(tn + (tid >> 3)) * (Kdim) + (c) * BKT + (tid & 7) * 8; \
        uint32_t d0 = sbase + so + (uint32_t)((tid >> 3) * ROWB + (tid & 7) * 16);        \
        _Pragma("unroll")                                                                 \
        for (int r = 0; r < 4; ++r) {                                                     \
            cp_async16(d0 + (uint32_t)(r * 32 * ROWB),        a0 + (size_t)(r * 32) * (Kdim)); \
            cp_async16(d0 + ABYT + (uint32_t)(r * 32 * ROWB), b0 + (size_t)(r * 32) * (Kdim)); \
        }                                                                                 \
    }

// fp32-acc 2-stage mainloop (R9/R12 winner)
#define GEMM_MAINLOOP(Ab, Bb, Kdim)                                                       \
    {                                                                                     \
        const int NC = (Kdim) / BKT;                                                      \
        CPLOAD(Ab, Bb, Kdim, 0, 0) CP_COMMIT();                                           \
        CPLOAD(Ab, Bb, Kdim, 1, 1) CP_COMMIT();                                           \
        for (int c = 0; c < NC; ++c) {                                                    \
            if (c + 1 < NC) { CP_WAIT(1); } else { CP_WAIT(0); }                          \
            __syncthreads();                                                              \
            const uint32_t so = (uint32_t)((c & 1) * STGB);                               \
            _Pragma("unroll")                                                             \
            for (int kk = 0; kk < BKT; kk += 16) {                                        \
                uint32_t af[4][4];                                                        \
                uint32_t bf[4][2];                                                        \
                _Pragma("unroll")                                                         \
                for (int mt = 0; mt < 4; ++mt)                                            \
                    ldsm_x4_u(af[mt][0], af[mt][1], af[mt][2], af[mt][3],                 \
                              sbase + so + (uint32_t)((wm + mt * 16 + (lane & 15)) * ROWB \
                                                      + (kk + ((lane >> 4) << 3)) * 2));  \
                _Pragma("unroll")                                                         \
                for (int nb = 0; nb < 2; ++nb) {                                          \
                    uint32_t r0, r1, r2, r3;                                              \
                    ldsm_x4_u(r0, r1, r2, r3,                                             \
                              sbase + so + ABYT + (uint32_t)((wn + nb * 16 + (lane & 15)) * ROWB \
                                                      + (kk + ((lane >> 4) << 3)) * 2));  \
                    bf[nb * 2 + 0][0] = r0; bf[nb * 2 + 0][1] = r2;                       \
                    bf[nb * 2 + 1][0] = r1; bf[nb * 2 + 1][1] = r3;                       \
                }                                                                         \
                _Pragma("unroll")                                                         \
                for (int mt = 0; mt < 4; ++mt)                                            \
                    _Pragma("unroll")                                                     \
                    for (int nt = 0; nt < 4; ++nt)                                        \
                        mma16816(acc[mt][nt], af[mt], bf[nt]);                            \
            }                                                                             \
            __syncthreads();                                                              \
            if (c + 2 < NC) { CPLOAD(Ab, Bb, Kdim, c + 2, (c & 1)) CP_COMMIT(); }         \
        }                                                                                 \
    }

// ---------------- GEMM1: V-transpose prologue + E = exp(QK^T/32 + mask) ------
// Epilogue stages the CTA's 128x128 fp32 mask tile into the (now free)
// pipeline smem with COALESCED float4 loads, then computes e = exp(s+m),
// stores E fp16, and emits per-CTA row-sum partials (deterministic).
// MROW = 132: multiple of 4 (float4-aligned rows) and 132 % 32 = 4 so the
// eight quad-rows of a warp map to distinct banks.
#define MROW 132

__global__ void __launch_bounds__(256, 2)
gemm_s(const __half* __restrict__ A, const __half* __restrict__ B,
       const float* __restrict__ V, __half* __restrict__ Vt,
       const float* __restrict__ mask,
       __half* __restrict__ E, float* __restrict__ RSpart)
{
    extern __shared__ char dsm[];
    const uint32_t sbase = smem_u32(dsm);
    __shared__ float rowpart[4][BM];

    const int b = blockIdx.z;
    const int tid  = threadIdx.x;
    const int wid  = tid >> 5;
    const int lane = tid & 31;

    // ---- V transpose prologue: one 32x32 tile per warp (proven in R14) ----
    {
        const int linear = blockIdx.y * gridDim.x + blockIdx.x;   // 0..255
        const int t  = linear * 8 + wid;                          // 0..2047
        const int e0 = (t & 31) * 32;
        const int j0 = (t >> 5) * 32;
        float* stg = reinterpret_cast<float*>(dsm) + wid * (32 * 33);
        const float* Vb  = V  + (size_t)b * SEQ * EMB;
        __half*      Vtb = Vt + (size_t)b * SEQ * EMB;
#pragma unroll 4
        for (int r = 0; r < 32; ++r)
            stg[r * 33 + lane] = Vb[(size_t)(j0 + r) * EMB + e0 + lane];
        __syncwarp();
#pragma unroll 4
        for (int r = 0; r < 32; ++r)
            Vtb[(size_t)(e0 + r) * SEQ + j0 + lane] = __float2half_rn(stg[lane * 33 + r]);
    }
    __syncthreads();   // staging smem reused by cp.async stages below

    const __half* Ab = A + (size_t)b * SEQ * EMB;
    const __half* Bb = B + (size_t)b * SEQ * EMB;
    __half*       Eb = E + (size_t)b * SEQ * SEQ;

    const int tm = blockIdx.y * BM;
    const int tn = blockIdx.x * BN;
    const int wm = (wid & 1) * 64;
    const int wn = (wid >> 1) * 32;

    float acc[4][4][4];
#pragma unroll
    for (int i = 0; i < 4; i++)
#pragma unroll
        for (int j = 0; j < 4; j++)
#pragma unroll
            for (int k = 0; k < 4; k++) acc[i][j][k] = 0.f;

    GEMM_MAINLOOP(Ab, Bb, EMB)

    // ---- epilogue: coalesced mask tile -> smem ----
    {
        float* msm = reinterpret_cast<float*>(dsm);
        const float* mb = mask + (size_t)b * SEQ * SEQ;
#pragma unroll
        for (int it = 0; it < 16; ++it) {
            int idx = it * 256 + tid;        // float4 index, 0..4095
            int rl = idx >> 5;               // 32 float4 per 128-col row
            int cl = (idx & 31) * 4;
            float4 v = *reinterpret_cast<const float4*>(&mb[(size_t)(tm + rl) * SEQ + tn + cl]);
            *reinterpret_cast<float4*>(&msm[rl * MROW + cl]) = v;
        }
    }
    __syncthreads();

    // ---- exp + store E + row-sum partials ----
    {
        const float* msm = reinterpret_cast<const float*>(dsm);
#pragma unroll
        for (int mt = 0; mt < 4; ++mt) {
            int rl = wm + mt * 16 + (lane >> 2);
            float s0 = 0.f, s1 = 0.f;
#pragma unroll
            for (int nt = 0; nt < 4; ++nt) {
                int cl = wn + nt * 8 + ((lane & 3) << 1);
                float2 m0 = *reinterpret_cast<const float2*>(&msm[rl * MROW + cl]);
                float2 m1 = *reinterpret_cast<const float2*>(&msm[(rl + 8) * MROW + cl]);
                float e00 = __expf(acc[mt][nt][0] + m0.x);
                float e01 = __expf(acc[mt][nt][1] + m0.y);
                float e10 = __expf(acc[mt][nt][2] + m1.x);
                float e11 = __expf(acc[mt][nt][3] + m1.y);
                int r = tm + rl, c = tn + cl;
                *reinterpret_cast<__half2*>(&Eb[(size_t)r * SEQ + c]) =
                    __floats2half2_rn(e00, e01);
                *reinterpret_cast<__half2*>(&Eb[(size_t)(r + 8) * SEQ + c]) =
                    __floats2half2_rn(e10, e11);
                s0 += e00 + e01;
                s1 += e10 + e11;
            }
            s0 += __shfl_xor_sync(0xffffffffu, s0, 1);
            s0 += __shfl_xor_sync(0xffffffffu, s0, 2);
            s1 += __shfl_xor_sync(0xffffffffu, s1, 1);
            s1 += __shfl_xor_sync(0xffffffffu, s1, 2);
            if ((lane & 3) == 0) {
                rowpart[wid >> 1][rl]     = s0;
                rowpart[wid >> 1][rl + 8] = s1;
            }
        }
    }
    __syncthreads();
    if (tid < BM) {
        float rs = rowpart[0][tid] + rowpart[1][tid] + rowpart[2][tid] + rowpart[3][tid];
        RSpart[(size_t)blockIdx.x * (BATCH * SEQ) + (size_t)b * SEQ + tm + tid] = rs;
    }
}

// ---------------- GEMM2: O = (E @ Vt^T) / rowsum, fp32 acc ------------------
__global__ void __launch_bounds__(256, 2)
gemm_o(const __half* __restrict__ A, const __half* __restrict__ B,
       float* __restrict__ C, const float* __restrict__ RSpart)
{
    extern __shared__ char dsm[];
    const uint32_t sbase = smem_u32(dsm);
    __shared__ float inv[BM];

    const int b = blockIdx.z;
    const __half* Ab = A + (size_t)b * SEQ * SEQ;   // E: K = SEQ
    const __half* Bb = B + (size_t)b * SEQ * EMB;   // Vt: K = SEQ
    float*        Cb = C + (size_t)b * SEQ * EMB;

    const int tm = blockIdx.y * BM;
    const int tn = blockIdx.x * BN;
    const int tid  = threadIdx.x;
    const int wid  = tid >> 5;
    const int lane = tid & 31;
    const int wm = (wid & 1) * 64;
    const int wn = (wid >> 1) * 32;

    // reciprocal row sums (16 deterministic partials per row)
    if (tid < BM) {
        float rs = 0.f;
#pragma unroll
        for (int i = 0; i < 16; ++i)
            rs += RSpart[(size_t)i * (BATCH * SEQ) + (size_t)b * SEQ + tm + tid];
        inv[tid] = 1.0f / rs;
    }
    // visibility of inv[] is guaranteed by the first __syncthreads in the mainloop

    float acc[4][4][4];
#pragma unroll
    for (int i = 0; i < 4; i++)
#pragma unroll
        for (int j = 0; j < 4; j++)
#pragma unroll
            for (int k = 0; k < 4; k++) acc[i][j][k] = 0.f;

    GEMM_MAINLOOP(Ab, Bb, SEQ)

#pragma unroll
    for (int mt = 0; mt < 4; ++mt) {
        int rl = wm + mt * 16 + (lane >> 2);
        float i0 = inv[rl];
        float i1 = inv[rl + 8];
        int r = tm + rl;
#pragma unroll
        for (int nt = 0; nt < 4; ++nt) {
            int c = tn + wn + nt * 8 + ((lane & 3) << 1);
            *reinterpret_cast<float2*>(&Cb[(size_t)r * EMB + c]) =
                make_float2(acc[mt][nt][0] * i0, acc[mt][nt][1] * i0);
            *reinterpret_cast<float2*>(&Cb[(size_t)(r + 8) * EMB + c]) =
                make_float2(acc[mt][nt][2] * i1, acc[mt][nt][3] * i1);
        }
    }
}

// ---------------- launch -----------------------------------------------------
extern "C" void kernel_launch(void* const* d_in, const int* in_sizes, int n_in,
                              void* d_out, int out_size)
{
    const float* Q    = (const float*)d_in[0];
    const float* K    = (const float*)d_in[1];
    const float* V    = (const float*)d_in[2];
    const float* mask = (const float*)d_in[3];
    float* out = (float*)d_out;

    void *pQh, *pKh, *pVt, *pE, *pRS;
    cudaGetSymbolAddress(&pQh, d_Qh);
    cudaGetSymbolAddress(&pKh, d_Kh);
    cudaGetSymbolAddress(&pVt, d_Vt);
    cudaGetSymbolAddress(&pE,  d_E);
    cudaGetSymbolAddress(&pRS, d_RS);

    cudaFuncSetAttribute(gemm_s, cudaFuncAttributeMaxDynamicSharedMemorySize, GEMM_DSMEM);
    cudaFuncSetAttribute(gemm_o, cudaFuncAttributeMaxDynamicSharedMemorySize, GEMM_DSMEM);

    // Q/K convert (single launch)
    prep<<<8192, 256>>>(Q, K, (__half*)pQh, (__half*)pKh);

    // V transpose (hidden) + E = exp(QK^T/32 + mask) + row-sum partials
    gemm_s<<<dim3(SEQ / BN, SEQ / BM, BATCH), 256, GEMM_DSMEM>>>(
        (const __half*)pQh, (const __half*)pKh, V, (__half*)pVt,
        mask, (__half*)pE, (float*)pRS);

    // O = (E @ V) / rowsum
    gemm_o<<<dim3(EMB / BN, SEQ / BM, BATCH), 256, GEMM_DSMEM>>>(
        (const __half*)pE, (const __half*)pVt, out, (const float*)pRS);
}